// round 7
// baseline (speedup 1.0000x reference)
#include <cuda_runtime.h>
#include <cuda_bf16.h>
#include <cstdint>

#define Bb 8
#define Cc 512
#define Tt 4
#define NN 256
#define LL 1024
#define HH 8
#define DD 64

typedef __nv_bfloat16 bf16;

// Scratch
__device__ bf16  g_wsp[3 * Cc * Cc];        // wp exact 3-way bf16 split
__device__ float g_wT[3 * Cc * Cc];         // wq/wk/wv transposed [w][c][o]
__device__ bf16  g_s0b[Bb * Cc * LL];       // proj spikes bf16 [b][c][l]
__device__ uint32_t g_mask[Bb * LL * 16];   // spike bitmask [b][l][16 words of c]
__device__ float g_y[3 * Bb * Cc * LL];     // qkv pre-activation fp32
__device__ bf16  g_qb[Bb * HH * LL * DD];   // q spikes [b][h][l][d]
__device__ bf16  g_kb[Bb * Cc * LL];        // k spikes [b][c][l]
__device__ bf16  g_vb[Bb * HH * LL * DD];   // v spikes [b][h][l][d]
__device__ bf16  g_sattnb[Bb * Cc * LL];    // attn spikes [b][c][l]

// ---------------------------------------------------------------------------
__device__ __forceinline__ uint32_t smem_u32(const void* p) {
    return (uint32_t)__cvta_generic_to_shared(p);
}
__device__ __forceinline__ void ldsm4(uint32_t* r, uint32_t a) {
    asm volatile("ldmatrix.sync.aligned.m8n8.x4.shared.b16 {%0,%1,%2,%3}, [%4];"
                 : "=r"(r[0]), "=r"(r[1]), "=r"(r[2]), "=r"(r[3]) : "r"(a));
}
__device__ __forceinline__ void ldsm4t(uint32_t* r, uint32_t a) {
    asm volatile("ldmatrix.sync.aligned.m8n8.x4.trans.shared.b16 {%0,%1,%2,%3}, [%4];"
                 : "=r"(r[0]), "=r"(r[1]), "=r"(r[2]), "=r"(r[3]) : "r"(a));
}
__device__ __forceinline__ void mma16816(float* c, const uint32_t* a, uint32_t b0, uint32_t b1) {
    asm volatile(
        "mma.sync.aligned.m16n8k16.row.col.f32.bf16.bf16.f32 "
        "{%0,%1,%2,%3}, {%4,%5,%6,%7}, {%8,%9}, {%0,%1,%2,%3};"
        : "+f"(c[0]), "+f"(c[1]), "+f"(c[2]), "+f"(c[3])
        : "r"(a[0]), "r"(a[1]), "r"(a[2]), "r"(a[3]), "r"(b0), "r"(b1));
}
__device__ __forceinline__ uint32_t packbf(float lo, float hi) {
    uint32_t l = (uint32_t)__bfloat16_as_ushort(__float2bfloat16(lo));
    uint32_t h = (uint32_t)__bfloat16_as_ushort(__float2bfloat16(hi));
    return l | (h << 16);
}

// ---------------------------------------------------------------------------
// Kernel 0a: exact 3-way bf16 split of wp.
// ---------------------------------------------------------------------------
__global__ void k_split_w(const float* __restrict__ wp) {
    int idx = blockIdx.x * blockDim.x + threadIdx.x;
    if (idx >= Cc * Cc) return;
    float w = wp[idx];
    bf16 hi = __float2bfloat16(w);
    float r1 = w - __bfloat162float(hi);
    bf16 mid = __float2bfloat16(r1);
    float r2 = r1 - __bfloat162float(mid);
    g_wsp[0 * Cc * Cc + idx] = hi;
    g_wsp[1 * Cc * Cc + idx] = mid;
    g_wsp[2 * Cc * Cc + idx] = __float2bfloat16(r2);
}

// ---------------------------------------------------------------------------
// Kernel 0b: transpose wq/wk/wv -> g_wT [w][c][o]
// ---------------------------------------------------------------------------
__global__ void k_transpose_w(const float* __restrict__ wq,
                              const float* __restrict__ wk,
                              const float* __restrict__ wv) {
    int w = blockIdx.z;
    const float* W = (w == 0) ? wq : (w == 1) ? wk : wv;
    __shared__ float sm[32][33];
    int c0 = blockIdx.x * 32, o0 = blockIdx.y * 32;
    int x = threadIdx.x, y0 = threadIdx.y;  // 32 x 8
#pragma unroll
    for (int k = 0; k < 4; k++) {
        int y = y0 + k * 8;
        sm[y][x] = W[(size_t)(o0 + y) * Cc + c0 + x];   // [o][c] coalesced read
    }
    __syncthreads();
#pragma unroll
    for (int k = 0; k < 4; k++) {
        int y = y0 + k * 8;
        g_wT[((size_t)w * Cc + c0 + y) * Cc + o0 + x] = sm[x][y];  // [c][o] coalesced write
    }
}

// ---------------------------------------------------------------------------
// Kernel 1: proj BN + multi-step LIF -> g_s0b
// ---------------------------------------------------------------------------
__global__ void k_bn_lif_proj(const float* __restrict__ x,
                              const float* __restrict__ gp,
                              const float* __restrict__ bpn,
                              const float* __restrict__ mp,
                              const float* __restrict__ vp) {
    int idx = blockIdx.x * blockDim.x + threadIdx.x;
    if (idx >= Bb * Cc * NN) return;
    int n = idx % NN;
    int c = (idx / NN) % Cc;
    int b = idx / (NN * Cc);

    float sc = gp[c] / sqrtf(vp[c] + 1e-5f);
    float sh = bpn[c] - mp[c] * sc;

    const float* xp = x + ((size_t)(b * Cc + c) * Tt) * NN + n;
    bf16* sp = g_s0b + (size_t)(b * Cc + c) * LL + n;

    float v = 0.0f;
#pragma unroll
    for (int t = 0; t < Tt; t++) {
        float xb = xp[(size_t)t * NN] * sc + sh;
        v = v + (xb - v) / 1.5f;
        float s = (v >= 1.0f) ? 1.0f : 0.0f;
        sp[(size_t)t * NN] = __float2bfloat16(s);
        if (s != 0.0f) v = 0.0f;
    }
}

// ---------------------------------------------------------------------------
// Kernel 1b: pack spikes into per-(b,l) 512-bit masks.
// CTA = (b, 64 l's). Phase A: ballot along l per channel. Phase B: 32x32 bit
// transpose to get per-l words over c.
// ---------------------------------------------------------------------------
__global__ __launch_bounds__(256) void k_pack_mask() {
    int b = blockIdx.y;
    int l0 = blockIdx.x * 64;
    int tid = threadIdx.x, lane = tid & 31, wrp = tid >> 5;
    __shared__ uint32_t Bsm[512][2];   // [c][l-half] bits over l

    for (int k = 0; k < 64; k++) {
        int c = wrp * 64 + k;
        const bf16* row = g_s0b + (size_t)(b * Cc + c) * LL + l0;
#pragma unroll
        for (int pass = 0; pass < 2; pass++) {
            unsigned short v = __bfloat16_as_ushort(row[pass * 32 + lane]);
            unsigned m = __ballot_sync(0xffffffffu, v != 0);
            if (lane == 0) Bsm[c][pass] = m;
        }
    }
    __syncthreads();

#pragma unroll
    for (int j = 0; j < 4; j++) {
        int flat = tid + 256 * j;      // 0..1023 = l*16 + W
        int l = flat >> 4, W = flat & 15;
        int lh = l >> 5, lb = l & 31;
        uint32_t word = 0;
#pragma unroll
        for (int cp = 0; cp < 32; cp++)
            word |= ((Bsm[W * 32 + cp][lh] >> lb) & 1u) << cp;
        g_mask[((size_t)b * LL + l0 + l) * 16 + W] = word;
    }
}

// ---------------------------------------------------------------------------
// Kernel 2 (SPARSE): qkv projection, value-identical to ascending-k fp32 FFMA.
// acc[o][l] += wT[c][o] for each set bit c (ascending), skipping zero spikes
// (exact: fma(W,0,acc)==acc, fma(W,1,acc)==acc+W).
// CTA: 128o x 128l; 8 warps x 16 l; lane owns 4 consecutive o.
// grid = (LL/128, Cc/128, 3*Bb)
// ---------------------------------------------------------------------------
__global__ __launch_bounds__(256) void k_gemm_qkv_sparse() {
    int z = blockIdx.z;
    int w = z >> 3, b = z & 7;
    const float* WT = g_wT + (size_t)w * Cc * Cc;   // [c][o]
    float* C = g_y + (size_t)z * Cc * LL;

    int o0 = blockIdx.y * 128, lt0 = blockIdx.x * 128;
    int tid = threadIdx.x, lane = tid & 31, wrp = tid >> 5;
    int lane4 = lane * 4;
    int lw0 = lt0 + wrp * 16;

    __shared__ float Wsm[64][128];   // [c_local][o]

    float acc[16][4];
#pragma unroll
    for (int i = 0; i < 16; i++)
#pragma unroll
        for (int j = 0; j < 4; j++) acc[i][j] = 0.0f;

    // reg-staged W block loads: 8 float4/thread, coalesced along o
    float4 pa[8];
#define PREFW(cb)                                                                 \
    {                                                                             \
        _Pragma("unroll") for (int k = 0; k < 8; k++) {                           \
            int f = tid + 256 * k;                                                \
            int cl = f >> 5, o4 = f & 31;                                         \
            pa[k] = *(const float4*)(WT + ((size_t)(cb) * 64 + cl) * Cc + o0 + o4 * 4); \
        }                                                                         \
    }
#define STOSW()                                                                   \
    {                                                                             \
        _Pragma("unroll") for (int k = 0; k < 8; k++) {                           \
            int f = tid + 256 * k;                                                \
            int cl = f >> 5, o4 = f & 31;                                         \
            *(float4*)&Wsm[cl][o4 * 4] = pa[k];                                   \
        }                                                                         \
    }

    const uint32_t* mbase = g_mask + ((size_t)b * LL + lw0) * 16;

    PREFW(0);
    STOSW();
    __syncthreads();

    for (int cb = 0; cb < 8; cb++) {
        if (cb < 7) PREFW(cb + 1);

#pragma unroll
        for (int li = 0; li < 16; li++) {
            unsigned long long m =
                *(const unsigned long long*)(mbase + (size_t)li * 16 + cb * 2);
            while (m) {
                int cp = __ffsll(m) - 1;
                m &= m - 1;
                float4 wv = *(const float4*)&Wsm[cp][lane4];
                acc[li][0] += wv.x;
                acc[li][1] += wv.y;
                acc[li][2] += wv.z;
                acc[li][3] += wv.w;
            }
        }

        __syncthreads();
        if (cb < 7) {
            STOSW();
            __syncthreads();
        }
    }
#undef PREFW
#undef STOSW

    // epilogue: 4 o-rows x 16 l per thread, float4 along l
#pragma unroll
    for (int oi = 0; oi < 4; oi++) {
        float* crow = C + (size_t)(o0 + lane4 + oi) * LL + lw0;
#pragma unroll
        for (int j = 0; j < 4; j++) {
            float4 v = make_float4(acc[4 * j][oi], acc[4 * j + 1][oi],
                                   acc[4 * j + 2][oi], acc[4 * j + 3][oi]);
            *(float4*)(crow + j * 4) = v;
        }
    }
}

// ---------------------------------------------------------------------------
// Kernel 3: per-branch BN + LIF with coalesced I/O (unchanged from R6).
// ---------------------------------------------------------------------------
__global__ __launch_bounds__(256) void k_bn_lif_qkv(
        const float* __restrict__ gq, const float* __restrict__ bq,
        const float* __restrict__ mq, const float* __restrict__ vq,
        const float* __restrict__ gk, const float* __restrict__ bk,
        const float* __restrict__ mk, const float* __restrict__ vk,
        const float* __restrict__ gv, const float* __restrict__ bv,
        const float* __restrict__ mv, const float* __restrict__ vv) {
    int z = blockIdx.z;
    int w = z / Bb, b = z % Bb;
    int h = blockIdx.y;
    int n0 = blockIdx.x * 32;
    int tid = threadIdx.x, lane = tid & 31, wrp = tid >> 5;

    const float *gg, *bb, *mm, *vvv;
    if (w == 0) { gg = gq; bb = bq; mm = mq; vvv = vq; }
    else if (w == 1) { gg = gk; bb = bk; mm = mk; vvv = vk; }
    else { gg = gv; bb = bv; mm = mv; vvv = vv; }

    const bool isK = (w == 1);
    __shared__ bf16 sm[Tt][32][66];

#pragma unroll
    for (int i = 0; i < 8; i++) {
        int od = wrp * 8 + i;
        int o = h * 64 + od;
        float sc = gg[o] / sqrtf(vvv[o] + 1e-5f);
        float sh = bb[o] - mm[o] * sc;
        const float* yp = g_y + (size_t)((w * Bb + b) * Cc + o) * LL + n0 + lane;

        float v = 0.0f;
#pragma unroll
        for (int t = 0; t < Tt; t++) {
            float yb = yp[(size_t)t * NN] * sc + sh;
            v = v + (yb - v) / 1.5f;
            float s = (v >= 1.0f) ? 1.0f : 0.0f;
            if (isK)
                g_kb[(size_t)(b * Cc + o) * LL + t * NN + n0 + lane] = __float2bfloat16(s);
            else
                sm[t][lane][od] = __float2bfloat16(s);
            if (s != 0.0f) v = 0.0f;
        }
    }

    if (!isK) {
        __syncthreads();
        bf16* dst = ((w == 0) ? g_qb : g_vb) + (size_t)(b * HH + h) * LL * DD;
#pragma unroll
        for (int j = 0; j < 16; j++) {
            int flat = tid + 256 * j;
            int row = flat >> 5, col = flat & 31;
            int t = row >> 5, n = row & 31;
            uint32_t val;
            memcpy(&val, &sm[t][n][col * 2], 4);
            *(uint32_t*)(dst + ((size_t)(t * NN + n0 + n)) * DD + col * 2) = val;
        }
    }
}

// ---------------------------------------------------------------------------
// Kernel 4: attention on tensor cores (exact: binary inputs, integer sums).
// ---------------------------------------------------------------------------
__global__ __launch_bounds__(256) void k_attn_mma() {
    int l0 = blockIdx.x * 128;
    int bh = blockIdx.y;
    int b = bh >> 3, h = bh & 7;

    const bf16* Q = g_qb + (size_t)bh * LL * DD;
    const bf16* K = g_kb + (size_t)(b * Cc + h * 64) * LL;
    const bf16* V = g_vb + (size_t)bh * LL * DD;

    __shared__ bf16 Qs[128 * 72];
    __shared__ bf16 Ks[64 * 64];
    __shared__ bf16 Vs[64 * 64];

    int tid = threadIdx.x, lane = tid & 31, warp = tid >> 5;
    const uint32_t sQ = smem_u32(Qs), sK = smem_u32(Ks), sV = smem_u32(Vs);

#pragma unroll
    for (int t = 0; t < 4; t++) {
        int id = tid + t * 256;
        int r = id >> 3, c = id & 7;
        uint4 qv = *(const uint4*)(Q + (size_t)(l0 + r) * DD + c * 8);
        *(uint4*)((char*)Qs + r * 144 + c * 16) = qv;
    }
    __syncthreads();

    uint32_t aq[4][4];
    {
        int row = warp * 16 + (lane & 15);
#pragma unroll
        for (int kc = 0; kc < 4; kc++)
            ldsm4(aq[kc], sQ + row * 144 + kc * 32 + (lane >> 4) * 16);
    }

    float oacc[8][4];
#pragma unroll
    for (int i = 0; i < 8; i++)
#pragma unroll
        for (int j = 0; j < 4; j++) oacc[i][j] = 0.0f;

    for (int k0 = 0; k0 < LL; k0 += 64) {
        __syncthreads();
#pragma unroll
        for (int t = 0; t < 2; t++) {
            int id = tid + t * 256;
            int r = id >> 3, c = id & 7;
            int x = c ^ (r & 7);
            uint4 kv = *(const uint4*)(K + (size_t)r * LL + k0 + c * 8);
            *(uint4*)((char*)Ks + r * 128 + x * 16) = kv;
            uint4 vv = *(const uint4*)(V + (size_t)(k0 + r) * DD + c * 8);
            *(uint4*)((char*)Vs + r * 128 + x * 16) = vv;
        }
        __syncthreads();

        float sacc[8][4];
#pragma unroll
        for (int i = 0; i < 8; i++)
#pragma unroll
            for (int j = 0; j < 4; j++) sacc[i][j] = 0.0f;
#pragma unroll
        for (int nb = 0; nb < 4; nb++) {
#pragma unroll
            for (int ks = 0; ks < 4; ks++) {
                uint32_t bf[4];
                int krow = ks * 16 + (lane & 7) + ((lane >> 3) & 1) * 8;
                int ch = nb * 2 + (lane >> 4);
                int x = ch ^ (krow & 7);
                ldsm4t(bf, sK + krow * 128 + x * 16);
                mma16816(sacc[nb * 2],     aq[ks], bf[0], bf[1]);
                mma16816(sacc[nb * 2 + 1], aq[ks], bf[2], bf[3]);
            }
        }
        uint32_t sa[4][4];
#pragma unroll
        for (int kb = 0; kb < 4; kb++) {
            sa[kb][0] = packbf(sacc[2 * kb][0],     sacc[2 * kb][1]);
            sa[kb][1] = packbf(sacc[2 * kb][2],     sacc[2 * kb][3]);
            sa[kb][2] = packbf(sacc[2 * kb + 1][0], sacc[2 * kb + 1][1]);
            sa[kb][3] = packbf(sacc[2 * kb + 1][2], sacc[2 * kb + 1][3]);
        }
#pragma unroll
        for (int nb = 0; nb < 4; nb++) {
#pragma unroll
            for (int kb = 0; kb < 4; kb++) {
                uint32_t bf[4];
                int krow = kb * 16 + (lane & 7) + ((lane >> 3) & 1) * 8;
                int ch = nb * 2 + (lane >> 4);
                int x = ch ^ (krow & 7);
                ldsm4t(bf, sV + krow * 128 + x * 16);
                mma16816(oacc[nb * 2],     sa[kb], bf[0], bf[1]);
                mma16816(oacc[nb * 2 + 1], sa[kb], bf[2], bf[3]);
            }
        }
    }

    int row = warp * 16 + (lane >> 2);
#pragma unroll
    for (int nj = 0; nj < 8; nj++) {
        int col = nj * 8 + (lane & 3) * 2;
#pragma unroll
        for (int e = 0; e < 4; e++) {
            int r = row + (e >> 1) * 8;
            int c = col + (e & 1);
            float o = oacc[nj][e] * 0.125f;
            float s = ((o / 1.5f - 1.0f) >= 0.0f) ? 1.0f : 0.0f;
            g_sattnb[((size_t)b * Cc + h * 64 + c) * LL + (l0 + r)] = __float2bfloat16(s);
        }
    }
}

// ---------------------------------------------------------------------------
// Kernel 5: output projection via 3-split bf16 MMA (after last threshold).
// ---------------------------------------------------------------------------
__global__ __launch_bounds__(256, 2) void k_gemm_out_mma(const float* __restrict__ bp,
                                                         float* __restrict__ out) {
    const bf16* A = g_wsp;
    const bf16* B = g_sattnb + (size_t)blockIdx.z * Cc * LL;
    float* C = out + (size_t)blockIdx.z * Cc * LL;

    __shared__ bf16 As[128 * 40];
    __shared__ bf16 Bs[32 * 128];

    const int tid = threadIdx.x;
    const int lane = tid & 31, warp = tid >> 5;
    const int wm = warp >> 1, wn = warp & 1;
    const int o0 = blockIdx.y * 128, l0 = blockIdx.x * 128;

    float acc[2][8][4];
#pragma unroll
    for (int i = 0; i < 2; i++)
#pragma unroll
        for (int j = 0; j < 8; j++)
#pragma unroll
            for (int k = 0; k < 4; k++) acc[i][j][k] = 0.0f;

    int aM[2], aK[2], bK[2], bX[2];
#pragma unroll
    for (int t = 0; t < 2; t++) {
        int id = tid + t * 256;
        aM[t] = id >> 2; aK[t] = id & 3;
        bK[t] = id >> 4; bX[t] = id & 15;
    }
    uint4 pa[2], pb[2];
    const uint32_t sA = smem_u32(As), sB = smem_u32(Bs);

#define LOADG(kk)                                                                      \
    {                                                                                  \
        int split = ((kk) * 32) >> 9;                                                  \
        int c0 = ((kk) * 32) & 511;                                                    \
        const bf16* Ab = A + (size_t)split * (Cc * Cc);                                \
        _Pragma("unroll") for (int t = 0; t < 2; t++)                                  \
            pa[t] = *(const uint4*)(Ab + (size_t)(o0 + aM[t]) * Cc + c0 + aK[t] * 8);  \
        _Pragma("unroll") for (int t = 0; t < 2; t++)                                  \
            pb[t] = *(const uint4*)(B + (size_t)(c0 + bK[t]) * LL + l0 + bX[t] * 8);   \
    }
#define STOS()                                                                         \
    {                                                                                  \
        _Pragma("unroll") for (int t = 0; t < 2; t++)                                  \
            *(uint4*)((char*)As + aM[t] * 80 + aK[t] * 16) = pa[t];                    \
        _Pragma("unroll") for (int t = 0; t < 2; t++) {                                \
            int k = bK[t];                                                             \
            int x = bX[t] ^ (k & 7);                                                   \
            *(uint4*)((char*)Bs + k * 256 + x * 16) = pb[t];                           \
        }                                                                              \
    }

    LOADG(0);
    STOS();

    for (int kk = 0; kk < 48; kk++) {
        __syncthreads();
        if (kk < 47) LOADG(kk + 1);
#pragma unroll
        for (int ks = 0; ks < 2; ks++) {
            uint32_t a[2][4];
#pragma unroll
            for (int mi = 0; mi < 2; mi++) {
                int row = wm * 32 + mi * 16 + (lane & 15);
                ldsm4(a[mi], sA + row * 80 + (ks * 16 + (lane >> 4) * 8) * 2);
            }
            uint32_t bfr[4][4];
#pragma unroll
            for (int nb = 0; nb < 4; nb++) {
                int krow = ks * 16 + (lane & 7) + ((lane >> 3) & 1) * 8;
                int x = (wn * 8 + nb * 2 + (lane >> 4)) ^ (krow & 7);
                ldsm4t(bfr[nb], sB + krow * 256 + x * 16);
            }
#pragma unroll
            for (int mi = 0; mi < 2; mi++)
#pragma unroll
                for (int nj = 0; nj < 8; nj++)
                    mma16816(acc[mi][nj], a[mi], bfr[nj >> 1][(nj & 1) * 2],
                             bfr[nj >> 1][(nj & 1) * 2 + 1]);
        }
        __syncthreads();
        if (kk < 47) STOS();
    }
#undef LOADG
#undef STOS

#pragma unroll
    for (int mi = 0; mi < 2; mi++) {
        int r0 = o0 + wm * 32 + mi * 16 + (lane >> 2);
        float bi0 = bp[r0];
        float bi1 = bp[r0 + 8];
#pragma unroll
        for (int nj = 0; nj < 8; nj++) {
            int cb = l0 + wn * 64 + nj * 8 + (lane & 3) * 2;
            float2 v0 = make_float2(acc[mi][nj][0] + bi0, acc[mi][nj][1] + bi0);
            float2 v1 = make_float2(acc[mi][nj][2] + bi1, acc[mi][nj][3] + bi1);
            *(float2*)&C[(size_t)r0 * LL + cb] = v0;
            *(float2*)&C[(size_t)(r0 + 8) * LL + cb] = v1;
        }
    }
}

// ---------------------------------------------------------------------------
extern "C" void kernel_launch(void* const* d_in, const int* in_sizes, int n_in,
                              void* d_out, int out_size) {
    const float* x   = (const float*)d_in[0];
    const float* wq  = (const float*)d_in[1];
    const float* wk  = (const float*)d_in[2];
    const float* wv  = (const float*)d_in[3];
    const float* wp  = (const float*)d_in[4];
    const float* bp  = (const float*)d_in[5];
    const float* gq  = (const float*)d_in[6];
    const float* bq  = (const float*)d_in[7];
    const float* mq  = (const float*)d_in[8];
    const float* vq  = (const float*)d_in[9];
    const float* gk  = (const float*)d_in[10];
    const float* bk  = (const float*)d_in[11];
    const float* mk  = (const float*)d_in[12];
    const float* vk  = (const float*)d_in[13];
    const float* gv  = (const float*)d_in[14];
    const float* bv  = (const float*)d_in[15];
    const float* mv  = (const float*)d_in[16];
    const float* vv  = (const float*)d_in[17];
    const float* gp  = (const float*)d_in[18];
    const float* bpn = (const float*)d_in[19];
    const float* mp  = (const float*)d_in[20];
    const float* vp  = (const float*)d_in[21];
    float* out = (float*)d_out;

    k_split_w<<<(Cc * Cc + 255) / 256, 256>>>(wp);
    k_transpose_w<<<dim3(Cc / 32, Cc / 32, 3), dim3(32, 8)>>>(wq, wk, wv);
    k_bn_lif_proj<<<(Bb * Cc * NN + 255) / 256, 256>>>(x, gp, bpn, mp, vp);
    k_pack_mask<<<dim3(LL / 64, Bb), 256>>>();
    k_gemm_qkv_sparse<<<dim3(LL / 128, Cc / 128, 3 * Bb), 256>>>();
    k_bn_lif_qkv<<<dim3(NN / 32, HH, 3 * Bb), 256>>>(gq, bq, mq, vq,
                                                     gk, bk, mk, vk,
                                                     gv, bv, mv, vv);
    k_attn_mma<<<dim3(LL / 128, Bb * HH), 256>>>();
    k_gemm_out_mma<<<dim3(LL / 128, Cc / 128, Bb), 256>>>(bp, out);
}

// round 8
// speedup vs baseline: 1.3402x; 1.3402x over previous
#include <cuda_runtime.h>
#include <cuda_bf16.h>
#include <cstdint>

#define Bb 8
#define Cc 512
#define Tt 4
#define NN 256
#define LL 1024
#define HH 8
#define DD 64

typedef __nv_bfloat16 bf16;
typedef unsigned long long u64;

// Scratch
__device__ bf16  g_wsp[3 * Cc * Cc];       // wp exact 3-way bf16 split
__device__ bf16  g_s0b[Bb * Cc * LL];      // proj spikes bf16 [b][c][l]
__device__ float g_y[3 * Bb * Cc * LL];    // qkv pre-activation fp32
__device__ bf16  g_qb[Bb * HH * LL * DD];  // q spikes [b][h][l][d]
__device__ bf16  g_kb[Bb * Cc * LL];       // k spikes [b][c][l]
__device__ bf16  g_vb[Bb * HH * LL * DD];  // v spikes [b][h][l][d]
__device__ bf16  g_sattnb[Bb * Cc * LL];   // attn spikes [b][c][l]

// ---------------------------------------------------------------------------
__device__ __forceinline__ uint32_t smem_u32(const void* p) {
    return (uint32_t)__cvta_generic_to_shared(p);
}
__device__ __forceinline__ void ldsm4(uint32_t* r, uint32_t a) {
    asm volatile("ldmatrix.sync.aligned.m8n8.x4.shared.b16 {%0,%1,%2,%3}, [%4];"
                 : "=r"(r[0]), "=r"(r[1]), "=r"(r[2]), "=r"(r[3]) : "r"(a));
}
__device__ __forceinline__ void ldsm4t(uint32_t* r, uint32_t a) {
    asm volatile("ldmatrix.sync.aligned.m8n8.x4.trans.shared.b16 {%0,%1,%2,%3}, [%4];"
                 : "=r"(r[0]), "=r"(r[1]), "=r"(r[2]), "=r"(r[3]) : "r"(a));
}
__device__ __forceinline__ void mma16816(float* c, const uint32_t* a, uint32_t b0, uint32_t b1) {
    asm volatile(
        "mma.sync.aligned.m16n8k16.row.col.f32.bf16.bf16.f32 "
        "{%0,%1,%2,%3}, {%4,%5,%6,%7}, {%8,%9}, {%0,%1,%2,%3};"
        : "+f"(c[0]), "+f"(c[1]), "+f"(c[2]), "+f"(c[3])
        : "r"(a[0]), "r"(a[1]), "r"(a[2]), "r"(a[3]), "r"(b0), "r"(b1));
}
__device__ __forceinline__ uint32_t packbf(float lo, float hi) {
    uint32_t l = (uint32_t)__bfloat16_as_ushort(__float2bfloat16(lo));
    uint32_t h = (uint32_t)__bfloat16_as_ushort(__float2bfloat16(hi));
    return l | (h << 16);
}
// --- packed f32x2 (Blackwell FFMA2; each half an independent fp32 fma) -----
__device__ __forceinline__ u64 pack2(float lo, float hi) {
    u64 r;
    asm("mov.b64 %0, {%1, %2};" : "=l"(r) : "f"(lo), "f"(hi));
    return r;
}
__device__ __forceinline__ void unpack2(float& lo, float& hi, u64 v) {
    asm("mov.b64 {%0, %1}, %2;" : "=f"(lo), "=f"(hi) : "l"(v));
}
__device__ __forceinline__ void fma2(u64& d, u64 a, u64 b) {
    asm("fma.rn.f32x2 %0, %1, %2, %0;" : "+l"(d) : "l"(a), "l"(b));
}

// ---------------------------------------------------------------------------
// Kernel 0: exact 3-way bf16 split of wp.
// ---------------------------------------------------------------------------
__global__ void k_split_w(const float* __restrict__ wp) {
    int idx = blockIdx.x * blockDim.x + threadIdx.x;
    if (idx >= Cc * Cc) return;
    float w = wp[idx];
    bf16 hi = __float2bfloat16(w);
    float r1 = w - __bfloat162float(hi);
    bf16 mid = __float2bfloat16(r1);
    float r2 = r1 - __bfloat162float(mid);
    g_wsp[0 * Cc * Cc + idx] = hi;
    g_wsp[1 * Cc * Cc + idx] = mid;
    g_wsp[2 * Cc * Cc + idx] = __float2bfloat16(r2);
}

// ---------------------------------------------------------------------------
// Kernel 1: proj BN + multi-step LIF -> g_s0b
// ---------------------------------------------------------------------------
__global__ void k_bn_lif_proj(const float* __restrict__ x,
                              const float* __restrict__ gp,
                              const float* __restrict__ bpn,
                              const float* __restrict__ mp,
                              const float* __restrict__ vp) {
    int idx = blockIdx.x * blockDim.x + threadIdx.x;
    if (idx >= Bb * Cc * NN) return;
    int n = idx % NN;
    int c = (idx / NN) % Cc;
    int b = idx / (NN * Cc);

    float sc = gp[c] / sqrtf(vp[c] + 1e-5f);
    float sh = bpn[c] - mp[c] * sc;

    const float* xp = x + ((size_t)(b * Cc + c) * Tt) * NN + n;
    bf16* sp = g_s0b + (size_t)(b * Cc + c) * LL + n;

    float v = 0.0f;
#pragma unroll
    for (int t = 0; t < Tt; t++) {
        float xb = xp[(size_t)t * NN] * sc + sh;
        v = v + (xb - v) / 1.5f;
        float s = (v >= 1.0f) ? 1.0f : 0.0f;
        sp[(size_t)t * NN] = __float2bfloat16(s);
        if (s != 0.0f) v = 0.0f;
    }
}

// ---------------------------------------------------------------------------
// Kernel 2: QKV projection, BITWISE fp32 (ascending k, single acc per elem),
// inner loop on packed fma.rn.f32x2 (pairs adjacent l outputs; each half is
// an independent sequential fp32 chain -> bit-identical per element).
// 128x128 tile, BK=16, 256 threads, 8x8/thread, double-buffered smem.
// grid = (LL/128, Cc/128, 3*Bb)
// ---------------------------------------------------------------------------
__global__ __launch_bounds__(256, 2) void k_gemm_qkv_f32(const float* __restrict__ wq,
                                                         const float* __restrict__ wk,
                                                         const float* __restrict__ wv) {
    int z = blockIdx.z;
    int w = z >> 3, b = z & 7;
    const float* A = (w == 0) ? wq : (w == 1) ? wk : wv;
    const bf16* B = g_s0b + (size_t)b * Cc * LL;
    float* C = g_y + (size_t)z * Cc * LL;

    int o0 = blockIdx.y * 128, l0 = blockIdx.x * 128;
    int tid = threadIdx.x;
    int tx = tid & 15, ty = tid >> 4;

    __shared__ float As[2][16][128];
    __shared__ float Bs[2][16][128];

    int aRow = tid >> 1, aK = (tid & 1) * 8;
    int bRow = tid >> 4, bCh = tid & 15;

    u64 accp[8][4];   // [o-row i][l-pair jp] = (acc[i][2jp], acc[i][2jp+1])
#pragma unroll
    for (int i = 0; i < 8; i++)
#pragma unroll
        for (int j = 0; j < 4; j++) accp[i][j] = 0ull;

    float4 pa0, pa1;
    uint4 pbv;

#define PREF(k0)                                                              \
    {                                                                         \
        pa0 = *(const float4*)(A + (size_t)(o0 + aRow) * Cc + (k0) + aK);     \
        pa1 = *(const float4*)(A + (size_t)(o0 + aRow) * Cc + (k0) + aK + 4); \
        pbv = *(const uint4*)(B + (size_t)((k0) + bRow) * LL + l0 + bCh * 8); \
    }
#define STORE(buf)                                                              \
    {                                                                           \
        As[buf][aK + 0][aRow] = pa0.x; As[buf][aK + 1][aRow] = pa0.y;           \
        As[buf][aK + 2][aRow] = pa0.z; As[buf][aK + 3][aRow] = pa0.w;           \
        As[buf][aK + 4][aRow] = pa1.x; As[buf][aK + 5][aRow] = pa1.y;           \
        As[buf][aK + 6][aRow] = pa1.z; As[buf][aK + 7][aRow] = pa1.w;           \
        const __nv_bfloat162* pb2 = (const __nv_bfloat162*)&pbv;                \
        float4 f0, f1;                                                          \
        { float2 t0 = __bfloat1622float2(pb2[0]); f0.x = t0.x; f0.y = t0.y; }   \
        { float2 t1 = __bfloat1622float2(pb2[1]); f0.z = t1.x; f0.w = t1.y; }   \
        { float2 t2 = __bfloat1622float2(pb2[2]); f1.x = t2.x; f1.y = t2.y; }   \
        { float2 t3 = __bfloat1622float2(pb2[3]); f1.z = t3.x; f1.w = t3.y; }   \
        *(float4*)&Bs[buf][bRow][bCh * 8] = f0;                                 \
        *(float4*)&Bs[buf][bRow][bCh * 8 + 4] = f1;                             \
    }

    PREF(0);
    STORE(0);
    __syncthreads();

    for (int kt = 0; kt < 32; kt++) {
        int cur = kt & 1;
        if (kt < 31) PREF((kt + 1) * 16);
#pragma unroll
        for (int kk = 0; kk < 16; kk++) {
            float a[8], bv[8];
            *(float4*)&a[0]  = *(const float4*)&As[cur][kk][ty * 8];
            *(float4*)&a[4]  = *(const float4*)&As[cur][kk][ty * 8 + 4];
            *(float4*)&bv[0] = *(const float4*)&Bs[cur][kk][tx * 8];
            *(float4*)&bv[4] = *(const float4*)&Bs[cur][kk][tx * 8 + 4];
            u64 bp2[4], ad[8];
#pragma unroll
            for (int jp = 0; jp < 4; jp++) bp2[jp] = pack2(bv[2 * jp], bv[2 * jp + 1]);
#pragma unroll
            for (int i = 0; i < 8; i++) ad[i] = pack2(a[i], a[i]);
#pragma unroll
            for (int i = 0; i < 8; i++)
#pragma unroll
                for (int jp = 0; jp < 4; jp++) fma2(accp[i][jp], ad[i], bp2[jp]);
        }
        if (kt < 31) { STORE(!cur); }
        __syncthreads();
    }
#undef PREF
#undef STORE

#pragma unroll
    for (int i = 0; i < 8; i++) {
        int o = o0 + ty * 8 + i;
        float r[8];
#pragma unroll
        for (int jp = 0; jp < 4; jp++) unpack2(r[2 * jp], r[2 * jp + 1], accp[i][jp]);
        *(float4*)&C[(size_t)o * LL + l0 + tx * 8]     = *(float4*)&r[0];
        *(float4*)&C[(size_t)o * LL + l0 + tx * 8 + 4] = *(float4*)&r[4];
    }
}

// ---------------------------------------------------------------------------
// Kernel 3: per-branch BN + LIF with coalesced I/O.
// ---------------------------------------------------------------------------
__global__ __launch_bounds__(256) void k_bn_lif_qkv(
        const float* __restrict__ gq, const float* __restrict__ bq,
        const float* __restrict__ mq, const float* __restrict__ vq,
        const float* __restrict__ gk, const float* __restrict__ bk,
        const float* __restrict__ mk, const float* __restrict__ vk,
        const float* __restrict__ gv, const float* __restrict__ bv,
        const float* __restrict__ mv, const float* __restrict__ vv) {
    int z = blockIdx.z;
    int w = z / Bb, b = z % Bb;
    int h = blockIdx.y;
    int n0 = blockIdx.x * 32;
    int tid = threadIdx.x, lane = tid & 31, wrp = tid >> 5;

    const float *gg, *bb, *mm, *vvv;
    if (w == 0) { gg = gq; bb = bq; mm = mq; vvv = vq; }
    else if (w == 1) { gg = gk; bb = bk; mm = mk; vvv = vk; }
    else { gg = gv; bb = bv; mm = mv; vvv = vv; }

    const bool isK = (w == 1);
    __shared__ bf16 sm[Tt][32][66];

#pragma unroll
    for (int i = 0; i < 8; i++) {
        int od = wrp * 8 + i;
        int o = h * 64 + od;
        float sc = gg[o] / sqrtf(vvv[o] + 1e-5f);
        float sh = bb[o] - mm[o] * sc;
        const float* yp = g_y + (size_t)((w * Bb + b) * Cc + o) * LL + n0 + lane;

        float v = 0.0f;
#pragma unroll
        for (int t = 0; t < Tt; t++) {
            float yb = yp[(size_t)t * NN] * sc + sh;
            v = v + (yb - v) / 1.5f;
            float s = (v >= 1.0f) ? 1.0f : 0.0f;
            if (isK)
                g_kb[(size_t)(b * Cc + o) * LL + t * NN + n0 + lane] = __float2bfloat16(s);
            else
                sm[t][lane][od] = __float2bfloat16(s);
            if (s != 0.0f) v = 0.0f;
        }
    }

    if (!isK) {
        __syncthreads();
        bf16* dst = ((w == 0) ? g_qb : g_vb) + (size_t)(b * HH + h) * LL * DD;
#pragma unroll
        for (int j = 0; j < 16; j++) {
            int flat = tid + 256 * j;
            int row = flat >> 5, col = flat & 31;
            int t = row >> 5, n = row & 31;
            uint32_t val;
            memcpy(&val, &sm[t][n][col * 2], 4);
            *(uint32_t*)(dst + ((size_t)(t * NN + n0 + n)) * DD + col * 2) = val;
        }
    }
}

// ---------------------------------------------------------------------------
// Kernel 4: attention on tensor cores (exact: binary inputs, integer sums).
// ---------------------------------------------------------------------------
__global__ __launch_bounds__(256) void k_attn_mma() {
    int l0 = blockIdx.x * 128;
    int bh = blockIdx.y;
    int b = bh >> 3, h = bh & 7;

    const bf16* Q = g_qb + (size_t)bh * LL * DD;
    const bf16* K = g_kb + (size_t)(b * Cc + h * 64) * LL;
    const bf16* V = g_vb + (size_t)bh * LL * DD;

    __shared__ bf16 Qs[128 * 72];
    __shared__ bf16 Ks[64 * 64];
    __shared__ bf16 Vs[64 * 64];

    int tid = threadIdx.x, lane = tid & 31, warp = tid >> 5;
    const uint32_t sQ = smem_u32(Qs), sK = smem_u32(Ks), sV = smem_u32(Vs);

#pragma unroll
    for (int t = 0; t < 4; t++) {
        int id = tid + t * 256;
        int r = id >> 3, c = id & 7;
        uint4 qv = *(const uint4*)(Q + (size_t)(l0 + r) * DD + c * 8);
        *(uint4*)((char*)Qs + r * 144 + c * 16) = qv;
    }
    __syncthreads();

    uint32_t aq[4][4];
    {
        int row = warp * 16 + (lane & 15);
#pragma unroll
        for (int kc = 0; kc < 4; kc++)
            ldsm4(aq[kc], sQ + row * 144 + kc * 32 + (lane >> 4) * 16);
    }

    float oacc[8][4];
#pragma unroll
    for (int i = 0; i < 8; i++)
#pragma unroll
        for (int j = 0; j < 4; j++) oacc[i][j] = 0.0f;

    for (int k0 = 0; k0 < LL; k0 += 64) {
        __syncthreads();
#pragma unroll
        for (int t = 0; t < 2; t++) {
            int id = tid + t * 256;
            int r = id >> 3, c = id & 7;
            int x = c ^ (r & 7);
            uint4 kv = *(const uint4*)(K + (size_t)r * LL + k0 + c * 8);
            *(uint4*)((char*)Ks + r * 128 + x * 16) = kv;
            uint4 vv = *(const uint4*)(V + (size_t)(k0 + r) * DD + c * 8);
            *(uint4*)((char*)Vs + r * 128 + x * 16) = vv;
        }
        __syncthreads();

        float sacc[8][4];
#pragma unroll
        for (int i = 0; i < 8; i++)
#pragma unroll
            for (int j = 0; j < 4; j++) sacc[i][j] = 0.0f;
#pragma unroll
        for (int nb = 0; nb < 4; nb++) {
#pragma unroll
            for (int ks = 0; ks < 4; ks++) {
                uint32_t bf[4];
                int krow = ks * 16 + (lane & 7) + ((lane >> 3) & 1) * 8;
                int ch = nb * 2 + (lane >> 4);
                int x = ch ^ (krow & 7);
                ldsm4t(bf, sK + krow * 128 + x * 16);
                mma16816(sacc[nb * 2],     aq[ks], bf[0], bf[1]);
                mma16816(sacc[nb * 2 + 1], aq[ks], bf[2], bf[3]);
            }
        }
        uint32_t sa[4][4];
#pragma unroll
        for (int kb = 0; kb < 4; kb++) {
            sa[kb][0] = packbf(sacc[2 * kb][0],     sacc[2 * kb][1]);
            sa[kb][1] = packbf(sacc[2 * kb][2],     sacc[2 * kb][3]);
            sa[kb][2] = packbf(sacc[2 * kb + 1][0], sacc[2 * kb + 1][1]);
            sa[kb][3] = packbf(sacc[2 * kb + 1][2], sacc[2 * kb + 1][3]);
        }
#pragma unroll
        for (int nb = 0; nb < 4; nb++) {
#pragma unroll
            for (int kb = 0; kb < 4; kb++) {
                uint32_t bf[4];
                int krow = kb * 16 + (lane & 7) + ((lane >> 3) & 1) * 8;
                int ch = nb * 2 + (lane >> 4);
                int x = ch ^ (krow & 7);
                ldsm4t(bf, sV + krow * 128 + x * 16);
                mma16816(oacc[nb * 2],     sa[kb], bf[0], bf[1]);
                mma16816(oacc[nb * 2 + 1], sa[kb], bf[2], bf[3]);
            }
        }
    }

    int row = warp * 16 + (lane >> 2);
#pragma unroll
    for (int nj = 0; nj < 8; nj++) {
        int col = nj * 8 + (lane & 3) * 2;
#pragma unroll
        for (int e = 0; e < 4; e++) {
            int r = row + (e >> 1) * 8;
            int c = col + (e & 1);
            float o = oacc[nj][e] * 0.125f;
            float s = ((o / 1.5f - 1.0f) >= 0.0f) ? 1.0f : 0.0f;
            g_sattnb[((size_t)b * Cc + h * 64 + c) * LL + (l0 + r)] = __float2bfloat16(s);
        }
    }
}

// ---------------------------------------------------------------------------
// Kernel 5: output projection via 3-split bf16 MMA (after last threshold).
// ---------------------------------------------------------------------------
__global__ __launch_bounds__(256, 2) void k_gemm_out_mma(const float* __restrict__ bp,
                                                         float* __restrict__ out) {
    const bf16* A = g_wsp;
    const bf16* B = g_sattnb + (size_t)blockIdx.z * Cc * LL;
    float* C = out + (size_t)blockIdx.z * Cc * LL;

    __shared__ bf16 As[128 * 40];
    __shared__ bf16 Bs[32 * 128];

    const int tid = threadIdx.x;
    const int lane = tid & 31, warp = tid >> 5;
    const int wm = warp >> 1, wn = warp & 1;
    const int o0 = blockIdx.y * 128, l0 = blockIdx.x * 128;

    float acc[2][8][4];
#pragma unroll
    for (int i = 0; i < 2; i++)
#pragma unroll
        for (int j = 0; j < 8; j++)
#pragma unroll
            for (int k = 0; k < 4; k++) acc[i][j][k] = 0.0f;

    int aM[2], aK[2], bK[2], bX[2];
#pragma unroll
    for (int t = 0; t < 2; t++) {
        int id = tid + t * 256;
        aM[t] = id >> 2; aK[t] = id & 3;
        bK[t] = id >> 4; bX[t] = id & 15;
    }
    uint4 pa[2], pb[2];
    const uint32_t sA = smem_u32(As), sB = smem_u32(Bs);

#define LOADG(kk)                                                                      \
    {                                                                                  \
        int split = ((kk) * 32) >> 9;                                                  \
        int c0 = ((kk) * 32) & 511;                                                    \
        const bf16* Ab = A + (size_t)split * (Cc * Cc);                                \
        _Pragma("unroll") for (int t = 0; t < 2; t++)                                  \
            pa[t] = *(const uint4*)(Ab + (size_t)(o0 + aM[t]) * Cc + c0 + aK[t] * 8);  \
        _Pragma("unroll") for (int t = 0; t < 2; t++)                                  \
            pb[t] = *(const uint4*)(B + (size_t)(c0 + bK[t]) * LL + l0 + bX[t] * 8);   \
    }
#define STOS()                                                                         \
    {                                                                                  \
        _Pragma("unroll") for (int t = 0; t < 2; t++)                                  \
            *(uint4*)((char*)As + aM[t] * 80 + aK[t] * 16) = pa[t];                    \
        _Pragma("unroll") for (int t = 0; t < 2; t++) {                                \
            int k = bK[t];                                                             \
            int x = bX[t] ^ (k & 7);                                                   \
            *(uint4*)((char*)Bs + k * 256 + x * 16) = pb[t];                           \
        }                                                                              \
    }

    LOADG(0);
    STOS();

    for (int kk = 0; kk < 48; kk++) {
        __syncthreads();
        if (kk < 47) LOADG(kk + 1);
#pragma unroll
        for (int ks = 0; ks < 2; ks++) {
            uint32_t a[2][4];
#pragma unroll
            for (int mi = 0; mi < 2; mi++) {
                int row = wm * 32 + mi * 16 + (lane & 15);
                ldsm4(a[mi], sA + row * 80 + (ks * 16 + (lane >> 4) * 8) * 2);
            }
            uint32_t bfr[4][4];
#pragma unroll
            for (int nb = 0; nb < 4; nb++) {
                int krow = ks * 16 + (lane & 7) + ((lane >> 3) & 1) * 8;
                int x = (wn * 8 + nb * 2 + (lane >> 4)) ^ (krow & 7);
                ldsm4t(bfr[nb], sB + krow * 256 + x * 16);
            }
#pragma unroll
            for (int mi = 0; mi < 2; mi++)
#pragma unroll
                for (int nj = 0; nj < 8; nj++)
                    mma16816(acc[mi][nj], a[mi], bfr[nj >> 1][(nj & 1) * 2],
                             bfr[nj >> 1][(nj & 1) * 2 + 1]);
        }
        __syncthreads();
        if (kk < 47) STOS();
    }
#undef LOADG
#undef STOS

#pragma unroll
    for (int mi = 0; mi < 2; mi++) {
        int r0 = o0 + wm * 32 + mi * 16 + (lane >> 2);
        float bi0 = bp[r0];
        float bi1 = bp[r0 + 8];
#pragma unroll
        for (int nj = 0; nj < 8; nj++) {
            int cb = l0 + wn * 64 + nj * 8 + (lane & 3) * 2;
            float2 v0 = make_float2(acc[mi][nj][0] + bi0, acc[mi][nj][1] + bi0);
            float2 v1 = make_float2(acc[mi][nj][2] + bi1, acc[mi][nj][3] + bi1);
            *(float2*)&C[(size_t)r0 * LL + cb] = v0;
            *(float2*)&C[(size_t)(r0 + 8) * LL + cb] = v1;
        }
    }
}

// ---------------------------------------------------------------------------
extern "C" void kernel_launch(void* const* d_in, const int* in_sizes, int n_in,
                              void* d_out, int out_size) {
    const float* x   = (const float*)d_in[0];
    const float* wq  = (const float*)d_in[1];
    const float* wk  = (const float*)d_in[2];
    const float* wv  = (const float*)d_in[3];
    const float* wp  = (const float*)d_in[4];
    const float* bp  = (const float*)d_in[5];
    const float* gq  = (const float*)d_in[6];
    const float* bq  = (const float*)d_in[7];
    const float* mq  = (const float*)d_in[8];
    const float* vq  = (const float*)d_in[9];
    const float* gk  = (const float*)d_in[10];
    const float* bk  = (const float*)d_in[11];
    const float* mk  = (const float*)d_in[12];
    const float* vk  = (const float*)d_in[13];
    const float* gv  = (const float*)d_in[14];
    const float* bv  = (const float*)d_in[15];
    const float* mv  = (const float*)d_in[16];
    const float* vv  = (const float*)d_in[17];
    const float* gp  = (const float*)d_in[18];
    const float* bpn = (const float*)d_in[19];
    const float* mp  = (const float*)d_in[20];
    const float* vp  = (const float*)d_in[21];
    float* out = (float*)d_out;

    k_split_w<<<(Cc * Cc + 255) / 256, 256>>>(wp);
    k_bn_lif_proj<<<(Bb * Cc * NN + 255) / 256, 256>>>(x, gp, bpn, mp, vp);
    k_gemm_qkv_f32<<<dim3(LL / 128, Cc / 128, 3 * Bb), 256>>>(wq, wk, wv);
    k_bn_lif_qkv<<<dim3(NN / 32, HH, 3 * Bb), 256>>>(gq, bq, mq, vq,
                                                     gk, bk, mk, vk,
                                                     gv, bv, mv, vv);
    k_attn_mma<<<dim3(LL / 128, Bb * HH), 256>>>();
    k_gemm_out_mma<<<dim3(LL / 128, Cc / 128, Bb), 256>>>(bp, out);
}

// round 9
// speedup vs baseline: 1.3760x; 1.0267x over previous
#include <cuda_runtime.h>
#include <cuda_bf16.h>
#include <cstdint>

#define Bb 8
#define Cc 512
#define Tt 4
#define NN 256
#define LL 1024
#define HH 8
#define DD 64

#define EPSY 3e-4f
#define FLAG_CAP (1 << 20)

typedef __nv_bfloat16 bf16;

// Scratch
__device__ bf16  g_wsp[4 * 3 * Cc * Cc];   // [mat(q,k,v,p)][split][o][c] exact 3-way bf16
__device__ bf16  g_s0b[Bb * Cc * LL];      // proj spikes bf16 [b][c][l]
__device__ float g_y[3 * Bb * Cc * LL];    // qkv pre-activation fp32
__device__ bf16  g_qb[Bb * HH * LL * DD];  // q spikes [b][h][l][d]
__device__ bf16  g_kb[Bb * Cc * LL];       // k spikes [b][c][l]
__device__ bf16  g_vb[Bb * HH * LL * DD];  // v spikes [b][h][l][d]
__device__ bf16  g_sattnb[Bb * Cc * LL];   // attn spikes [b][c][l]
__device__ unsigned int g_nflag;
__device__ unsigned int g_flag[FLAG_CAP];  // (w<<20)|(b<<17)|(o<<8)|n

// ---------------------------------------------------------------------------
__device__ __forceinline__ uint32_t smem_u32(const void* p) {
    return (uint32_t)__cvta_generic_to_shared(p);
}
__device__ __forceinline__ void ldsm4(uint32_t* r, uint32_t a) {
    asm volatile("ldmatrix.sync.aligned.m8n8.x4.shared.b16 {%0,%1,%2,%3}, [%4];"
                 : "=r"(r[0]), "=r"(r[1]), "=r"(r[2]), "=r"(r[3]) : "r"(a));
}
__device__ __forceinline__ void ldsm4t(uint32_t* r, uint32_t a) {
    asm volatile("ldmatrix.sync.aligned.m8n8.x4.trans.shared.b16 {%0,%1,%2,%3}, [%4];"
                 : "=r"(r[0]), "=r"(r[1]), "=r"(r[2]), "=r"(r[3]) : "r"(a));
}
__device__ __forceinline__ void mma16816(float* c, const uint32_t* a, uint32_t b0, uint32_t b1) {
    asm volatile(
        "mma.sync.aligned.m16n8k16.row.col.f32.bf16.bf16.f32 "
        "{%0,%1,%2,%3}, {%4,%5,%6,%7}, {%8,%9}, {%0,%1,%2,%3};"
        : "+f"(c[0]), "+f"(c[1]), "+f"(c[2]), "+f"(c[3])
        : "r"(a[0]), "r"(a[1]), "r"(a[2]), "r"(a[3]), "r"(b0), "r"(b1));
}
__device__ __forceinline__ uint32_t packbf(float lo, float hi) {
    uint32_t l = (uint32_t)__bfloat16_as_ushort(__float2bfloat16(lo));
    uint32_t h = (uint32_t)__bfloat16_as_ushort(__float2bfloat16(hi));
    return l | (h << 16);
}

// ---------------------------------------------------------------------------
// Kernel 0: exact 3-way bf16 split of wq,wk,wv,wp (8+8+8 bits >= fp32's 24).
// ---------------------------------------------------------------------------
__global__ void k_split_w(const float* __restrict__ wq, const float* __restrict__ wk,
                          const float* __restrict__ wv, const float* __restrict__ wp) {
    int idx = blockIdx.x * blockDim.x + threadIdx.x;
    if (idx >= 4 * Cc * Cc) return;
    int m = idx / (Cc * Cc);
    int rc = idx % (Cc * Cc);
    const float* W = (m == 0) ? wq : (m == 1) ? wk : (m == 2) ? wv : wp;
    float w = W[rc];
    bf16 hi = __float2bfloat16(w);
    float r1 = w - __bfloat162float(hi);
    bf16 mid = __float2bfloat16(r1);
    float r2 = r1 - __bfloat162float(mid);
    g_wsp[(size_t)(m * 3 + 0) * Cc * Cc + rc] = hi;
    g_wsp[(size_t)(m * 3 + 1) * Cc * Cc + rc] = mid;
    g_wsp[(size_t)(m * 3 + 2) * Cc * Cc + rc] = __float2bfloat16(r2);
}

__global__ void k_zero_flags() { g_nflag = 0; }

// ---------------------------------------------------------------------------
// Kernel 1: proj BN + multi-step LIF -> g_s0b (bitwise reference path)
// ---------------------------------------------------------------------------
__global__ void k_bn_lif_proj(const float* __restrict__ x,
                              const float* __restrict__ gp,
                              const float* __restrict__ bpn,
                              const float* __restrict__ mp,
                              const float* __restrict__ vp) {
    int idx = blockIdx.x * blockDim.x + threadIdx.x;
    if (idx >= Bb * Cc * NN) return;
    int n = idx % NN;
    int c = (idx / NN) % Cc;
    int b = idx / (NN * Cc);

    float sc = gp[c] / sqrtf(vp[c] + 1e-5f);
    float sh = bpn[c] - mp[c] * sc;

    const float* xp = x + ((size_t)(b * Cc + c) * Tt) * NN + n;
    bf16* sp = g_s0b + (size_t)(b * Cc + c) * LL + n;

    float v = 0.0f;
#pragma unroll
    for (int t = 0; t < Tt; t++) {
        float xb = xp[(size_t)t * NN] * sc + sh;
        v = v + (xb - v) / 1.5f;
        float s = (v >= 1.0f) ? 1.0f : 0.0f;
        sp[(size_t)t * NN] = __float2bfloat16(s);
        if (s != 0.0f) v = 0.0f;
    }
}

// ---------------------------------------------------------------------------
// Tensor-core GEMM core (validated): C[512,1024] = A(3 splits, K'=1536) @ B
// ---------------------------------------------------------------------------
__device__ __forceinline__ void gemm_core(const bf16* __restrict__ A,
                                          const bf16* __restrict__ B,
                                          float* __restrict__ C,
                                          const float* __restrict__ bias) {
    __shared__ bf16 As[128 * 40];
    __shared__ bf16 Bs[32 * 128];

    const int tid = threadIdx.x;
    const int lane = tid & 31, warp = tid >> 5;
    const int wm = warp >> 1, wn = warp & 1;
    const int o0 = blockIdx.y * 128, l0 = blockIdx.x * 128;

    float acc[2][8][4];
#pragma unroll
    for (int i = 0; i < 2; i++)
#pragma unroll
        for (int j = 0; j < 8; j++)
#pragma unroll
            for (int k = 0; k < 4; k++) acc[i][j][k] = 0.0f;

    int aM[2], aK[2], bK[2], bX[2];
#pragma unroll
    for (int t = 0; t < 2; t++) {
        int id = tid + t * 256;
        aM[t] = id >> 2; aK[t] = id & 3;
        bK[t] = id >> 4; bX[t] = id & 15;
    }
    uint4 pa[2], pb[2];
    const uint32_t sA = smem_u32(As), sB = smem_u32(Bs);

#define LOADG(kk)                                                                      \
    {                                                                                  \
        int split = ((kk) * 32) >> 9;                                                  \
        int c0 = ((kk) * 32) & 511;                                                    \
        const bf16* Ab = A + (size_t)split * (Cc * Cc);                                \
        _Pragma("unroll") for (int t = 0; t < 2; t++)                                  \
            pa[t] = *(const uint4*)(Ab + (size_t)(o0 + aM[t]) * Cc + c0 + aK[t] * 8);  \
        _Pragma("unroll") for (int t = 0; t < 2; t++)                                  \
            pb[t] = *(const uint4*)(B + (size_t)(c0 + bK[t]) * LL + l0 + bX[t] * 8);   \
    }
#define STOS()                                                                         \
    {                                                                                  \
        _Pragma("unroll") for (int t = 0; t < 2; t++)                                  \
            *(uint4*)((char*)As + aM[t] * 80 + aK[t] * 16) = pa[t];                    \
        _Pragma("unroll") for (int t = 0; t < 2; t++) {                                \
            int k = bK[t];                                                             \
            int x = bX[t] ^ (k & 7);                                                   \
            *(uint4*)((char*)Bs + k * 256 + x * 16) = pb[t];                           \
        }                                                                              \
    }

    LOADG(0);
    STOS();

    for (int kk = 0; kk < 48; kk++) {
        __syncthreads();
        if (kk < 47) LOADG(kk + 1);
#pragma unroll
        for (int ks = 0; ks < 2; ks++) {
            uint32_t a[2][4];
#pragma unroll
            for (int mi = 0; mi < 2; mi++) {
                int row = wm * 32 + mi * 16 + (lane & 15);
                ldsm4(a[mi], sA + row * 80 + (ks * 16 + (lane >> 4) * 8) * 2);
            }
            uint32_t bfr[4][4];
#pragma unroll
            for (int nb = 0; nb < 4; nb++) {
                int krow = ks * 16 + (lane & 7) + ((lane >> 3) & 1) * 8;
                int x = (wn * 8 + nb * 2 + (lane >> 4)) ^ (krow & 7);
                ldsm4t(bfr[nb], sB + krow * 256 + x * 16);
            }
#pragma unroll
            for (int mi = 0; mi < 2; mi++)
#pragma unroll
                for (int nj = 0; nj < 8; nj++)
                    mma16816(acc[mi][nj], a[mi], bfr[nj >> 1][(nj & 1) * 2],
                             bfr[nj >> 1][(nj & 1) * 2 + 1]);
        }
        __syncthreads();
        if (kk < 47) STOS();
    }
#undef LOADG
#undef STOS

#pragma unroll
    for (int mi = 0; mi < 2; mi++) {
        int r0 = o0 + wm * 32 + mi * 16 + (lane >> 2);
        float bi0 = bias ? bias[r0] : 0.0f;
        float bi1 = bias ? bias[r0 + 8] : 0.0f;
#pragma unroll
        for (int nj = 0; nj < 8; nj++) {
            int cb = l0 + wn * 64 + nj * 8 + (lane & 3) * 2;
            float2 v0 = make_float2(acc[mi][nj][0] + bi0, acc[mi][nj][1] + bi0);
            float2 v1 = make_float2(acc[mi][nj][2] + bi1, acc[mi][nj][3] + bi1);
            *(float2*)&C[(size_t)r0 * LL + cb] = v0;
            *(float2*)&C[(size_t)(r0 + 8) * LL + cb] = v1;
        }
    }
}

// grid = (LL/128, Cc/128, 3*Bb)
__global__ __launch_bounds__(256, 2) void k_gemm_qkv_mma() {
    int z = blockIdx.z;
    int w = z >> 3, b = z & 7;
    gemm_core(g_wsp + (size_t)w * 3 * Cc * Cc,
              g_s0b + (size_t)b * Cc * LL,
              g_y + (size_t)z * Cc * LL, nullptr);
}

// grid = (LL/128, Cc/128, Bb)
__global__ __launch_bounds__(256, 2) void k_gemm_out_mma(const float* __restrict__ bp,
                                                         float* __restrict__ out) {
    gemm_core(g_wsp + (size_t)3 * 3 * Cc * Cc,
              g_sattnb + (size_t)blockIdx.z * Cc * LL,
              out + (size_t)blockIdx.z * Cc * LL, bp);
}

// ---------------------------------------------------------------------------
// Kernel 3: per-branch BN + LIF (coalesced), with certified-margin flagging.
// Error bound on v: e <- e/3 + (2/3)*|sc|*EPSY ; flag chain if |v-1| < e.
// ---------------------------------------------------------------------------
__global__ __launch_bounds__(256) void k_bn_lif_qkv(
        const float* __restrict__ gq, const float* __restrict__ bq,
        const float* __restrict__ mq, const float* __restrict__ vq,
        const float* __restrict__ gk, const float* __restrict__ bk,
        const float* __restrict__ mk, const float* __restrict__ vk,
        const float* __restrict__ gv, const float* __restrict__ bv,
        const float* __restrict__ mv, const float* __restrict__ vv) {
    int z = blockIdx.z;
    int w = z / Bb, b = z % Bb;
    int h = blockIdx.y;
    int n0 = blockIdx.x * 32;
    int tid = threadIdx.x, lane = tid & 31, wrp = tid >> 5;

    const float *gg, *bb, *mm, *vvv;
    if (w == 0) { gg = gq; bb = bq; mm = mq; vvv = vq; }
    else if (w == 1) { gg = gk; bb = bk; mm = mk; vvv = vk; }
    else { gg = gv; bb = bv; mm = mv; vvv = vv; }

    const bool isK = (w == 1);
    __shared__ bf16 sm[Tt][32][66];

#pragma unroll
    for (int i = 0; i < 8; i++) {
        int od = wrp * 8 + i;
        int o = h * 64 + od;
        float sc = gg[o] / sqrtf(vvv[o] + 1e-5f);
        float sh = bb[o] - mm[o] * sc;
        const float* yp = g_y + (size_t)((w * Bb + b) * Cc + o) * LL + n0 + lane;

        float de = (2.0f / 3.0f) * fabsf(sc) * EPSY;
        float e = 0.0f;
        bool flagged = false;

        float v = 0.0f;
#pragma unroll
        for (int t = 0; t < Tt; t++) {
            float yb = yp[(size_t)t * NN] * sc + sh;
            v = v + (yb - v) / 1.5f;
            e = e * (1.0f / 3.0f) + de;
            if (fabsf(v - 1.0f) < e) flagged = true;
            float s = (v >= 1.0f) ? 1.0f : 0.0f;
            if (isK)
                g_kb[(size_t)(b * Cc + o) * LL + t * NN + n0 + lane] = __float2bfloat16(s);
            else
                sm[t][lane][od] = __float2bfloat16(s);
            if (s != 0.0f) { v = 0.0f; e = 0.0f; }
        }
        if (flagged) {
            unsigned int pos = atomicAdd(&g_nflag, 1u);
            if (pos < FLAG_CAP)
                g_flag[pos] = ((unsigned)w << 20) | ((unsigned)b << 17) |
                              ((unsigned)o << 8) | (unsigned)(n0 + lane);
        }
    }

    if (!isK) {
        __syncthreads();
        bf16* dst = ((w == 0) ? g_qb : g_vb) + (size_t)(b * HH + h) * LL * DD;
#pragma unroll
        for (int j = 0; j < 16; j++) {
            int flat = tid + 256 * j;
            int row = flat >> 5, col = flat & 31;
            int t = row >> 5, n = row & 31;
            uint32_t val;
            memcpy(&val, &sm[t][n][col * 2], 4);
            *(uint32_t*)(dst + ((size_t)(t * NN + n0 + n)) * DD + col * 2) = val;
        }
    }
}

// ---------------------------------------------------------------------------
// Kernel 3f: exact fallback for flagged chains — bitwise ascending-k fp32
// dot products + BN + LIF; overwrites the 4 spike outputs of the chain.
// ---------------------------------------------------------------------------
__global__ void k_fallback(
        const float* __restrict__ wq, const float* __restrict__ wk,
        const float* __restrict__ wv,
        const float* __restrict__ gq, const float* __restrict__ bq,
        const float* __restrict__ mq, const float* __restrict__ vq,
        const float* __restrict__ gk, const float* __restrict__ bk,
        const float* __restrict__ mk, const float* __restrict__ vk,
        const float* __restrict__ gv, const float* __restrict__ bv,
        const float* __restrict__ mv, const float* __restrict__ vv) {
    unsigned int total = g_nflag;
    if (total > FLAG_CAP) total = FLAG_CAP;
    for (unsigned int i = blockIdx.x * blockDim.x + threadIdx.x; i < total;
         i += gridDim.x * blockDim.x) {
        unsigned int enc = g_flag[i];
        int n = enc & 255;
        int o = (enc >> 8) & 511;
        int b = (enc >> 17) & 7;
        int w = enc >> 20;

        const float* W = (w == 0) ? wq : (w == 1) ? wk : wv;
        const float* Wrow = W + (size_t)o * Cc;
        const bf16* sbase = g_s0b + (size_t)b * Cc * LL + n;

        float acc0 = 0.0f, acc1 = 0.0f, acc2 = 0.0f, acc3 = 0.0f;
#pragma unroll 8
        for (int c = 0; c < Cc; c++) {
            float wv_ = Wrow[c];
            const bf16* sp = sbase + (size_t)c * LL;
            acc0 += wv_ * __bfloat162float(sp[0 * NN]);
            acc1 += wv_ * __bfloat162float(sp[1 * NN]);
            acc2 += wv_ * __bfloat162float(sp[2 * NN]);
            acc3 += wv_ * __bfloat162float(sp[3 * NN]);
        }
        float y[4] = {acc0, acc1, acc2, acc3};

        const float *gg, *bb, *mm, *vvv;
        if (w == 0) { gg = gq; bb = bq; mm = mq; vvv = vq; }
        else if (w == 1) { gg = gk; bb = bk; mm = mk; vvv = vk; }
        else { gg = gv; bb = bv; mm = mv; vvv = vv; }

        float sc = gg[o] / sqrtf(vvv[o] + 1e-5f);
        float sh = bb[o] - mm[o] * sc;
        int h = o >> 6, dd = o & 63;

        float v = 0.0f;
#pragma unroll
        for (int t = 0; t < Tt; t++) {
            float yb = y[t] * sc + sh;
            v = v + (yb - v) / 1.5f;
            float s = (v >= 1.0f) ? 1.0f : 0.0f;
            if (w == 1)
                g_kb[(size_t)(b * Cc + o) * LL + t * NN + n] = __float2bfloat16(s);
            else {
                bf16* base = (w == 0) ? g_qb : g_vb;
                base[((size_t)(b * HH + h) * LL + t * NN + n) * DD + dd] =
                    __float2bfloat16(s);
            }
            if (s != 0.0f) v = 0.0f;
        }
    }
}

// ---------------------------------------------------------------------------
// Kernel 4: attention on tensor cores (exact: binary inputs, integer sums).
// ---------------------------------------------------------------------------
__global__ __launch_bounds__(256) void k_attn_mma() {
    int l0 = blockIdx.x * 128;
    int bh = blockIdx.y;
    int b = bh >> 3, h = bh & 7;

    const bf16* Q = g_qb + (size_t)bh * LL * DD;
    const bf16* K = g_kb + (size_t)(b * Cc + h * 64) * LL;
    const bf16* V = g_vb + (size_t)bh * LL * DD;

    __shared__ bf16 Qs[128 * 72];
    __shared__ bf16 Ks[64 * 64];
    __shared__ bf16 Vs[64 * 64];

    int tid = threadIdx.x, lane = tid & 31, warp = tid >> 5;
    const uint32_t sQ = smem_u32(Qs), sK = smem_u32(Ks), sV = smem_u32(Vs);

#pragma unroll
    for (int t = 0; t < 4; t++) {
        int id = tid + t * 256;
        int r = id >> 3, c = id & 7;
        uint4 qv = *(const uint4*)(Q + (size_t)(l0 + r) * DD + c * 8);
        *(uint4*)((char*)Qs + r * 144 + c * 16) = qv;
    }
    __syncthreads();

    uint32_t aq[4][4];
    {
        int row = warp * 16 + (lane & 15);
#pragma unroll
        for (int kc = 0; kc < 4; kc++)
            ldsm4(aq[kc], sQ + row * 144 + kc * 32 + (lane >> 4) * 16);
    }

    float oacc[8][4];
#pragma unroll
    for (int i = 0; i < 8; i++)
#pragma unroll
        for (int j = 0; j < 4; j++) oacc[i][j] = 0.0f;

    for (int k0 = 0; k0 < LL; k0 += 64) {
        __syncthreads();
#pragma unroll
        for (int t = 0; t < 2; t++) {
            int id = tid + t * 256;
            int r = id >> 3, c = id & 7;
            int x = c ^ (r & 7);
            uint4 kv = *(const uint4*)(K + (size_t)r * LL + k0 + c * 8);
            *(uint4*)((char*)Ks + r * 128 + x * 16) = kv;
            uint4 vv = *(const uint4*)(V + (size_t)(k0 + r) * DD + c * 8);
            *(uint4*)((char*)Vs + r * 128 + x * 16) = vv;
        }
        __syncthreads();

        float sacc[8][4];
#pragma unroll
        for (int i = 0; i < 8; i++)
#pragma unroll
            for (int j = 0; j < 4; j++) sacc[i][j] = 0.0f;
#pragma unroll
        for (int nb = 0; nb < 4; nb++) {
#pragma unroll
            for (int ks = 0; ks < 4; ks++) {
                uint32_t bf[4];
                int krow = ks * 16 + (lane & 7) + ((lane >> 3) & 1) * 8;
                int ch = nb * 2 + (lane >> 4);
                int x = ch ^ (krow & 7);
                ldsm4t(bf, sK + krow * 128 + x * 16);
                mma16816(sacc[nb * 2],     aq[ks], bf[0], bf[1]);
                mma16816(sacc[nb * 2 + 1], aq[ks], bf[2], bf[3]);
            }
        }
        uint32_t sa[4][4];
#pragma unroll
        for (int kb = 0; kb < 4; kb++) {
            sa[kb][0] = packbf(sacc[2 * kb][0],     sacc[2 * kb][1]);
            sa[kb][1] = packbf(sacc[2 * kb][2],     sacc[2 * kb][3]);
            sa[kb][2] = packbf(sacc[2 * kb + 1][0], sacc[2 * kb + 1][1]);
            sa[kb][3] = packbf(sacc[2 * kb + 1][2], sacc[2 * kb + 1][3]);
        }
#pragma unroll
        for (int nb = 0; nb < 4; nb++) {
#pragma unroll
            for (int kb = 0; kb < 4; kb++) {
                uint32_t bf[4];
                int krow = kb * 16 + (lane & 7) + ((lane >> 3) & 1) * 8;
                int ch = nb * 2 + (lane >> 4);
                int x = ch ^ (krow & 7);
                ldsm4t(bf, sV + krow * 128 + x * 16);
                mma16816(oacc[nb * 2],     sa[kb], bf[0], bf[1]);
                mma16816(oacc[nb * 2 + 1], sa[kb], bf[2], bf[3]);
            }
        }
    }

    int row = warp * 16 + (lane >> 2);
#pragma unroll
    for (int nj = 0; nj < 8; nj++) {
        int col = nj * 8 + (lane & 3) * 2;
#pragma unroll
        for (int e = 0; e < 4; e++) {
            int r = row + (e >> 1) * 8;
            int c = col + (e & 1);
            float o = oacc[nj][e] * 0.125f;
            float s = ((o / 1.5f - 1.0f) >= 0.0f) ? 1.0f : 0.0f;
            g_sattnb[((size_t)b * Cc + h * 64 + c) * LL + (l0 + r)] = __float2bfloat16(s);
        }
    }
}

// ---------------------------------------------------------------------------
extern "C" void kernel_launch(void* const* d_in, const int* in_sizes, int n_in,
                              void* d_out, int out_size) {
    const float* x   = (const float*)d_in[0];
    const float* wq  = (const float*)d_in[1];
    const float* wk  = (const float*)d_in[2];
    const float* wv  = (const float*)d_in[3];
    const float* wp  = (const float*)d_in[4];
    const float* bp  = (const float*)d_in[5];
    const float* gq  = (const float*)d_in[6];
    const float* bq  = (const float*)d_in[7];
    const float* mq  = (const float*)d_in[8];
    const float* vq  = (const float*)d_in[9];
    const float* gk  = (const float*)d_in[10];
    const float* bk  = (const float*)d_in[11];
    const float* mk  = (const float*)d_in[12];
    const float* vk  = (const float*)d_in[13];
    const float* gv  = (const float*)d_in[14];
    const float* bv  = (const float*)d_in[15];
    const float* mv  = (const float*)d_in[16];
    const float* vv  = (const float*)d_in[17];
    const float* gp  = (const float*)d_in[18];
    const float* bpn = (const float*)d_in[19];
    const float* mp  = (const float*)d_in[20];
    const float* vp  = (const float*)d_in[21];
    float* out = (float*)d_out;

    k_split_w<<<(4 * Cc * Cc + 255) / 256, 256>>>(wq, wk, wv, wp);
    k_zero_flags<<<1, 1>>>();
    k_bn_lif_proj<<<(Bb * Cc * NN + 255) / 256, 256>>>(x, gp, bpn, mp, vp);
    k_gemm_qkv_mma<<<dim3(LL / 128, Cc / 128, 3 * Bb), 256>>>();
    k_bn_lif_qkv<<<dim3(NN / 32, HH, 3 * Bb), 256>>>(gq, bq, mq, vq,
                                                     gk, bk, mk, vk,
                                                     gv, bv, mv, vv);
    k_fallback<<<64, 256>>>(wq, wk, wv, gq, bq, mq, vq,
                            gk, bk, mk, vk, gv, bv, mv, vv);
    k_attn_mma<<<dim3(LL / 128, Bb * HH), 256>>>();
    k_gemm_out_mma<<<dim3(LL / 128, Cc / 128, Bb), 256>>>(bp, out);
}